// round 5
// baseline (speedup 1.0000x reference)
#include <cuda_runtime.h>
#include <cstdint>

#define NUSERS 100000
#define E 64
#define P 128
#define NSHARD 16
#define MSZ 512
#define WD 64
#define RR 4
#define INSZ 256
#define BB 256
#define SS 128
#define IND 384
#define QO 256

#define SCP 516
#define MSP 68
#define CH 64   // mem rows per staged chunk
#define NCH 8

__device__ float g_pe[BB * P];
__device__ float g_q[(size_t)BB * SS * QO];
__device__ int g_uid[BB];
__device__ float g_memh[NSHARD * MSZ * WD];
__device__ float g_meml[NSHARD * MSZ * WD];

// --- normalize user_id (handles int32 or int64 storage) ---
__global__ void k_uid(const int* __restrict__ u) {
    int s = 2;
#pragma unroll
    for (int i = 0; i < 8; i++)
        if (u[2 * i + 1] != 0) s = 1;
    int b = blockIdx.x * blockDim.x + threadIdx.x;
    if (b < BB) g_uid[b] = u[b * s];
}

__device__ __forceinline__ uint32_t t32(float x) {
    uint32_t u;
    asm("cvt.rna.tf32.f32 %0, %1;" : "=r"(u) : "f"(x));
    return u;
}
__device__ __forceinline__ void spl(float x, uint32_t& h, uint32_t& l) {
    h = t32(x);
    l = t32(x - __uint_as_float(h));
}
__device__ __forceinline__ void mma8(float d[4], const uint32_t a[4], uint32_t b0, uint32_t b1) {
    asm volatile(
        "mma.sync.aligned.m16n8k8.row.col.f32.tf32.tf32.f32 "
        "{%0,%1,%2,%3}, {%4,%5,%6,%7}, {%8,%9}, {%0,%1,%2,%3};"
        : "+f"(d[0]), "+f"(d[1]), "+f"(d[2]), "+f"(d[3])
        : "r"(a[0]), "r"(a[1]), "r"(a[2]), "r"(a[3]), "r"(b0), "r"(b1));
}

// --- pre-split memory into tf32 hi/lo (runs once per launch, tiny) ---
__global__ void k_split(const float* __restrict__ mem) {
    int i = blockIdx.x * blockDim.x + threadIdx.x;
    if (i < NSHARD * MSZ * WD) {
        float v = mem[i];
        uint32_t h, l;
        spl(v, h, l);
        g_memh[i] = __uint_as_float(h);
        g_meml[i] = __uint_as_float(l);
    }
}

// --- pe = table[uid] @ W_proc + b_proc ---
__global__ void k_pe(const float* __restrict__ tab, const float* __restrict__ Wp,
                     const float* __restrict__ bp) {
    __shared__ float ue[E];
    int b = blockIdx.x;
    int t = threadIdx.x;
    int uid = g_uid[b];
    if (t < E) ue[t] = tab[(size_t)uid * E + t];
    __syncthreads();
    float acc = bp[t];
#pragma unroll
    for (int e = 0; e < E; e++) acc += ue[e] * Wp[e * P + t];
    g_pe[b * P + t] = acc;
}

// --- q = concat(x, pe) @ Wq[sid]  (scalar tiled GEMM, known-good) ---
__global__ void k_qgemm(const float* __restrict__ x, const float* __restrict__ Wq) {
    __shared__ float As[64][17];
    __shared__ float Bs[16][64];
    int b = blockIdx.z;
    int n0 = blockIdx.x * 64, m0 = blockIdx.y * 64;
    int sid = ((unsigned)g_uid[b]) % NSHARD;
    const float* Wg = Wq + (size_t)sid * IND * QO;
    int tid = threadIdx.x;
    int tx = tid & 15, ty = tid >> 4;
    float acc[4][4] = {};
    const float* xb = x + ((size_t)b * SS + m0) * INSZ;

    for (int k0 = 0; k0 < IND; k0 += 16) {
        {
            int idx = tid * 4;
            int row = idx >> 4, kk = idx & 15;
            if (k0 < INSZ) {
                float4 v = *(const float4*)&xb[row * INSZ + k0 + kk];
                As[row][kk] = v.x; As[row][kk + 1] = v.y;
                As[row][kk + 2] = v.z; As[row][kk + 3] = v.w;
            } else {
                const float* pe = g_pe + b * P + (k0 - INSZ);
                As[row][kk] = pe[kk]; As[row][kk + 1] = pe[kk + 1];
                As[row][kk + 2] = pe[kk + 2]; As[row][kk + 3] = pe[kk + 3];
            }
        }
        {
            int idx = tid * 4;
            int kk = idx >> 6, nn = idx & 63;
            float4 v = *(const float4*)&Wg[(size_t)(k0 + kk) * QO + n0 + nn];
            *(float4*)&Bs[kk][nn] = v;
        }
        __syncthreads();
#pragma unroll
        for (int kk = 0; kk < 16; kk++) {
            float a[4];
#pragma unroll
            for (int i = 0; i < 4; i++) a[i] = As[ty * 4 + i][kk];
            float4 bv = *(const float4*)&Bs[kk][tx * 4];
            float bb[4] = {bv.x, bv.y, bv.z, bv.w};
#pragma unroll
            for (int i = 0; i < 4; i++)
#pragma unroll
                for (int j = 0; j < 4; j++) acc[i][j] += a[i] * bb[j];
        }
        __syncthreads();
    }
    float* qb = g_q + ((size_t)b * SS + m0) * QO + n0;
#pragma unroll
    for (int i = 0; i < 4; i++) {
        float4 v = {acc[i][0], acc[i][1], acc[i][2], acc[i][3]};
        *(float4*)&qb[(size_t)(ty * 4 + i) * QO + tx * 4] = v;
    }
}

// ---------------- fused attention via mma.sync tf32, pre-split B ----------------
// block = (b, 8 s-positions) = 32 rows. grid (16, B), 256 threads, 2 CTA/SM.
__global__ __launch_bounds__(256, 2) void k_attn(float* __restrict__ out) {
    extern __shared__ float sm[];
    float* sc = sm;                 // [32][516]
    float* msh = sc + 32 * SCP;     // [64][68]
    float* msl = msh + CH * MSP;    // [64][68]
    float* qs = msl + CH * MSP;     // [32][68]

    int tid = threadIdx.x;
    int lane = tid & 31, warp = tid >> 5;
    int g = lane >> 2, c = lane & 3;
    int rt = warp >> 2;
    int wq = warp & 3;
    int b = blockIdx.y;
    int s0 = blockIdx.x * 8;
    int sid = ((unsigned)g_uid[b]) % NSHARD;
    const float* Mh = g_memh + (size_t)sid * MSZ * WD;
    const float* Ml = g_meml + (size_t)sid * MSZ * WD;

    // stage q: qs[row][w]
    const float* qsrc = g_q + ((size_t)b * SS + s0) * QO;
    for (int i = tid; i < 32 * 16; i += 256) {
        int row = i >> 4, w4 = (i & 15) * 4;
        float4 v = *(const float4*)&qsrc[(size_t)(row >> 2) * QO + (row & 3) * WD + w4];
        *(float4*)&qs[row * MSP + w4] = v;
    }

    uint32_t ah[8][4], al[8][4];

    // ---- phase 1: scores[32,512] ----
    for (int ch = 0; ch < NCH; ch++) {
        for (int i = tid; i < CH * 16; i += 256) {
            int m = i >> 4, w4 = (i & 15) * 4;
            size_t go = (size_t)(ch * CH + m) * WD + w4;
            *(float4*)&msh[m * MSP + w4] = *(const float4*)&Mh[go];
            *(float4*)&msl[m * MSP + w4] = *(const float4*)&Ml[go];
        }
        __syncthreads();
        if (ch == 0) {
#pragma unroll
            for (int k = 0; k < 8; k++) {
                float a0 = qs[(rt * 16 + g) * MSP + k * 8 + c];
                float a1 = qs[(rt * 16 + g + 8) * MSP + k * 8 + c];
                float a2 = qs[(rt * 16 + g) * MSP + k * 8 + c + 4];
                float a3 = qs[(rt * 16 + g + 8) * MSP + k * 8 + c + 4];
                spl(a0, ah[k][0], al[k][0]);
                spl(a1, ah[k][1], al[k][1]);
                spl(a2, ah[k][2], al[k][2]);
                spl(a3, ah[k][3], al[k][3]);
            }
        }
#pragma unroll
        for (int nt = 0; nt < 2; nt++) {
            int n0 = wq * 16 + nt * 8;
            float d[4] = {0.f, 0.f, 0.f, 0.f};
#pragma unroll
            for (int k = 0; k < 8; k++) {
                uint32_t bh0 = __float_as_uint(msh[(n0 + g) * MSP + k * 8 + c]);
                uint32_t bh1 = __float_as_uint(msh[(n0 + g) * MSP + k * 8 + c + 4]);
                uint32_t bl0 = __float_as_uint(msl[(n0 + g) * MSP + k * 8 + c]);
                uint32_t bl1 = __float_as_uint(msl[(n0 + g) * MSP + k * 8 + c + 4]);
                mma8(d, ah[k], bh0, bh1);
                mma8(d, ah[k], bl0, bl1);
                mma8(d, al[k], bh0, bh1);
            }
            int mg = ch * CH + n0 + 2 * c;
            float2 v01 = {d[0], d[1]};
            float2 v23 = {d[2], d[3]};
            *(float2*)&sc[(rt * 16 + g) * SCP + mg] = v01;
            *(float2*)&sc[(rt * 16 + g + 8) * SCP + mg] = v23;
        }
        __syncthreads();
    }

    // ---- softmax over m per row; warp handles 4 rows ----
    for (int rr = 0; rr < 4; rr++) {
        int row = warp * 4 + rr;
        float* srow = sc + row * SCP;
        float vals[16];
        float mx = -1e30f;
#pragma unroll
        for (int j = 0; j < 16; j++) {
            vals[j] = srow[lane + 32 * j];
            mx = fmaxf(mx, vals[j]);
        }
#pragma unroll
        for (int o = 16; o > 0; o >>= 1) mx = fmaxf(mx, __shfl_xor_sync(0xffffffffu, mx, o));
        float sum = 0.f;
#pragma unroll
        for (int j = 0; j < 16; j++) {
            vals[j] = __expf(vals[j] - mx);
            sum += vals[j];
        }
#pragma unroll
        for (int o = 16; o > 0; o >>= 1) sum += __shfl_xor_sync(0xffffffffu, sum, o);
        float inv = 1.f / sum;
#pragma unroll
        for (int j = 0; j < 16; j++) srow[lane + 32 * j] = vals[j] * inv;
        if (b == BB - 1) {
            float* fs = out + (size_t)BB * SS * RR * WD + (size_t)(s0 * 4 + row) * MSZ;
#pragma unroll
            for (int j = 0; j < 16; j++) fs[lane + 32 * j] = vals[j] * inv;
        }
    }

    // ---- phase 2: read[32,64] = wts @ mem, 2-pass tf32 ----
    float acc[2][4];
#pragma unroll
    for (int nt = 0; nt < 2; nt++)
#pragma unroll
        for (int j = 0; j < 4; j++) acc[nt][j] = 0.f;

    for (int ch = 0; ch < NCH; ch++) {
        __syncthreads();
        for (int i = tid; i < CH * 16; i += 256) {
            int m = i >> 4, w4 = (i & 15) * 4;
            size_t go = (size_t)(ch * CH + m) * WD + w4;
            *(float4*)&msh[m * MSP + w4] = *(const float4*)&Mh[go];
            *(float4*)&msl[m * MSP + w4] = *(const float4*)&Ml[go];
        }
        __syncthreads();
#pragma unroll
        for (int kt = 0; kt < 8; kt++) {
            int kg = ch * CH + kt * 8;
            uint32_t wh[4];
            wh[0] = t32(sc[(rt * 16 + g) * SCP + kg + c]);
            wh[1] = t32(sc[(rt * 16 + g + 8) * SCP + kg + c]);
            wh[2] = t32(sc[(rt * 16 + g) * SCP + kg + c + 4]);
            wh[3] = t32(sc[(rt * 16 + g + 8) * SCP + kg + c + 4]);
#pragma unroll
            for (int nt = 0; nt < 2; nt++) {
                int n0 = wq * 16 + nt * 8;
                uint32_t bh0 = __float_as_uint(msh[(kt * 8 + c) * MSP + n0 + g]);
                uint32_t bh1 = __float_as_uint(msh[(kt * 8 + c + 4) * MSP + n0 + g]);
                uint32_t bl0 = __float_as_uint(msl[(kt * 8 + c) * MSP + n0 + g]);
                uint32_t bl1 = __float_as_uint(msl[(kt * 8 + c + 4) * MSP + n0 + g]);
                mma8(acc[nt], wh, bh0, bh1);
                mma8(acc[nt], wh, bl0, bl1);
            }
        }
    }

    // ---- epilogue ----
    float* ob = out + ((size_t)b * 512 + s0 * 4) * WD;
#pragma unroll
    for (int nt = 0; nt < 2; nt++) {
        int wcol = wq * 16 + nt * 8 + 2 * c;
        float2 v01 = {acc[nt][0], acc[nt][1]};
        float2 v23 = {acc[nt][2], acc[nt][3]};
        *(float2*)&ob[(size_t)(rt * 16 + g) * WD + wcol] = v01;
        *(float2*)&ob[(size_t)(rt * 16 + g + 8) * WD + wcol] = v23;
    }
}

extern "C" void kernel_launch(void* const* d_in, const int* in_sizes, int n_in,
                              void* d_out, int out_size) {
    const float* x = (const float*)d_in[0];
    const int* uid = (const int*)d_in[1];
    const float* tab = (const float*)d_in[2];
    const float* Wp = (const float*)d_in[3];
    const float* bp = (const float*)d_in[4];
    const float* Wq = (const float*)d_in[5];
    const float* memp = (const float*)d_in[6];
    float* out = (float*)d_out;

    k_uid<<<1, 256>>>(uid);
    k_split<<<(NSHARD * MSZ * WD + 511) / 512, 512>>>(memp);
    k_pe<<<BB, 128>>>(tab, Wp, bp);
    dim3 g2(4, 2, BB);
    k_qgemm<<<g2, 256>>>(x, Wq);

    const int smem_bytes = (32 * SCP + 2 * CH * MSP + 32 * MSP) * 4;
    cudaFuncSetAttribute(k_attn, cudaFuncAttributeMaxDynamicSharedMemorySize, smem_bytes);
    dim3 g3(16, BB);
    k_attn<<<g3, 256, smem_bytes>>>(out);
}